// round 4
// baseline (speedup 1.0000x reference)
#include <cuda_runtime.h>
#include <cuda_bf16.h>

// Problem shape: mlm_outputs [256, 4096, 30] f32, nsp_outputs [256,2] f32,
// mutation_matrix [30,30] f32 (mathematically cancels), mlm_targets [256*4096] i32,
// is_nexts [256] i32 (unused).
// Output (fp32): [mlm_predictions (B*S) | nsp_predictions (B) | loss (1)]
//
// Single fused kernel:
//  - per-block tile (256 rows x 30 f32) staged via coalesced float4 LDG -> smem
//    (1920 float4s = 7 full rounds of 256 threads + 128-thread tail)
//  - one row/thread, 15x LDS.64 reads, argmax + logsumexp NLL
//  - deterministic Q32.32 integer partial per block -> g_partial[blockIdx]
//  - self-resetting completion counter (atomicInc wrap) -> last block reduces
//    partials (integer adds: bit-exact any order), writes loss + NSP argmax.

#define VOCAB 30
#define ROWS_PER_BLOCK 256
#define THREADS 256
#define TILE_FLOATS (ROWS_PER_BLOCK * VOCAB)   // 7680 floats = 1920 float4
#define TILE_F4     (TILE_FLOATS / 4)          // 1920
#define FULL_ROUNDS (TILE_F4 / THREADS)        // 7
#define TAIL_F4     (TILE_F4 - FULL_ROUNDS * THREADS)  // 128
#define FIXED_SCALE 4294967296.0               // 2^32 Q32.32 fixed point
#define MAX_BLOCKS 8192

__device__ unsigned long long g_partial[MAX_BLOCKS];
__device__ unsigned int       g_done = 0;      // self-resets via atomicInc wrap

__global__ void __launch_bounds__(THREADS)
fused_kernel(const float* __restrict__ mlm,
             const float* __restrict__ nsp,
             const int*   __restrict__ tgt,
             float*       __restrict__ out,
             int n_rows, int B, int out_size)
{
    __shared__ float s[TILE_FLOATS];
    __shared__ unsigned long long warp_sums[THREADS / 32];
    __shared__ bool s_is_last;

    const int tid = threadIdx.x;

    // ---- Stage tile: 7 full rounds + 128-wide tail (all 1920 float4s) ----
    const size_t tile_base = (size_t)blockIdx.x * TILE_FLOATS;
    const float4* g4 = reinterpret_cast<const float4*>(mlm + tile_base);
    float4* s4 = reinterpret_cast<float4*>(s);
    #pragma unroll
    for (int i = 0; i < FULL_ROUNDS; ++i)
        s4[tid + i * THREADS] = g4[tid + i * THREADS];
    if (tid < TAIL_F4)
        s4[tid + FULL_ROUNDS * THREADS] = g4[tid + FULL_ROUNDS * THREADS];
    __syncthreads();

    // ---- One row per thread: 15x LDS.64 (tid*30 floats = tid*120 B, 8B aligned) ----
    const int row = blockIdx.x * ROWS_PER_BLOCK + tid;
    const int t   = tgt[row];

    float x[VOCAB];
    const float2* s2 = reinterpret_cast<const float2*>(s) + tid * (VOCAB / 2);
    #pragma unroll
    for (int i = 0; i < VOCAB / 2; ++i) {
        float2 v = s2[i];
        x[2 * i]     = v.x;
        x[2 * i + 1] = v.y;
    }

    // argmax (strict > keeps first max index, matching jnp.argmax)
    float mx = x[0];
    int   am = 0;
    #pragma unroll
    for (int i = 1; i < VOCAB; ++i)
        if (x[i] > mx) { mx = x[i]; am = i; }

    // logsumexp + pick x[target]
    float xt  = x[0];
    float sum = 0.0f;
    #pragma unroll
    for (int i = 0; i < VOCAB; ++i) {
        sum += __expf(x[i] - mx);
        if (i == t) xt = x[i];
    }
    float nll = __logf(sum) + mx - xt;   // logsumexp(x) - x[t] >= 0

    out[row] = (float)am;

    // ---- Deterministic masked accumulation: Q32.32 fixed point ----
    float contrib = (t != 0) ? nll : 0.0f;
    unsigned long long ll =
        (unsigned long long)__double2ll_rn((double)contrib * FIXED_SCALE);

    #pragma unroll
    for (int o = 16; o > 0; o >>= 1)
        ll += __shfl_down_sync(0xffffffffu, ll, o);
    if ((tid & 31) == 0) warp_sums[tid >> 5] = ll;
    __syncthreads();

    if (tid == 0) {
        unsigned long long total = 0ull;
        #pragma unroll
        for (int w = 0; w < THREADS / 32; ++w) total += warp_sums[w];
        g_partial[blockIdx.x] = total;            // every slot overwritten each launch
        __threadfence();                          // publish before counter bump
        unsigned int old = atomicInc(&g_done, gridDim.x - 1);  // wraps to 0: no init
        s_is_last = (old == gridDim.x - 1);
    }
    __syncthreads();

    // ---- Last block: reduce partials, write loss + NSP predictions ----
    if (s_is_last) {
        __threadfence();  // order partials reads after counter observation

        const int nblk = gridDim.x;
        unsigned long long acc = 0ull;
        for (int i = tid; i < nblk; i += THREADS)
            acc += g_partial[i];                  // integer adds: order-independent

        #pragma unroll
        for (int o = 16; o > 0; o >>= 1)
            acc += __shfl_down_sync(0xffffffffu, acc, o);
        if ((tid & 31) == 0) warp_sums[tid >> 5] = acc;
        __syncthreads();

        if (tid == 0) {
            unsigned long long total = 0ull;
            #pragma unroll
            for (int w = 0; w < THREADS / 32; ++w) total += warp_sums[w];
            double sdbl = (double)total / FIXED_SCALE;
            out[out_size - 1] = (float)(sdbl / (double)n_rows);
        }

        // NSP argmax: thread b handles batch element b (B <= THREADS)
        if (tid < B) {
            float v0 = nsp[2 * tid];
            float v1 = nsp[2 * tid + 1];
            out[n_rows + tid] = (v1 > v0) ? 1.0f : 0.0f;  // first-max tie-break
        }
    }
}

extern "C" void kernel_launch(void* const* d_in, const int* in_sizes, int n_in,
                              void* d_out, int out_size)
{
    const float* mlm = (const float*)d_in[0];   // [B*S*V] f32
    const float* nsp = (const float*)d_in[1];   // [B*2]   f32
    // d_in[2] = mutation_matrix (unused: weight cancels exactly)
    const int*   tgt = (const int*)d_in[3];     // [B*S]   i32
    // d_in[4] = is_nexts (unused)

    const int n_rows = in_sizes[3];             // B*S = 1048576
    const int B      = in_sizes[4];             // 256
    float* out = (float*)d_out;

    fused_kernel<<<n_rows / ROWS_PER_BLOCK, THREADS>>>(
        mlm, nsp, tgt, out, n_rows, B, out_size);
}